// round 9
// baseline (speedup 1.0000x reference)
#include <cuda_runtime.h>

// ARXCell, B = 16384 rows:
//   a2[b]       = dot(iw, itdl[b,0:2048]) + dot(ow, otdl[b,0:64]) + bias
//   itdl_new[b] = [ itdl[b,64:2048], input[b,0:64] ]
//   otdl_new[b] = [ otdl[b,1:64], a2[b] ]
//   outputs[b]  = a2[b]
//
// Output layout: [ outputs(16384) | itdl_new(16384*2048) | otdl_new(16384*64) ]
//
// One warp per row, 2048 CTAs x 256 threads. iw (8 KB) staged in shared
// memory once per CTA: weight reads leave the L1tex LDG queue entirely (LDS
// pipe instead), so the queue serves only the DRAM stream. Depth-6 rolling
// prefetch on the itdl stream (8 warps x 6 LDG x 4 lines = 192 wavefronts,
// under the ~248-entry L1tex queue).

#define BATCH       16384
#define DI          2048
#define DO          64
#define NIN         64
#define DI4         (DI / 4)     // 512 float4 per row
#define SHIFT4      (NIN / 4)    // 16 float4 shift
#define PF          6            // prefetch depth

__global__ __launch_bounds__(256, 4)
void arx_cell_kernel(const float* __restrict__ input,   // [B, 64]
                     const float* __restrict__ itdl,    // [B, 2048]
                     const float* __restrict__ otdl,    // [B, 64]
                     const float* __restrict__ iw,      // [2048]
                     const float* __restrict__ ow,      // [64]
                     const float* __restrict__ bias,    // [1]
                     float* __restrict__ out_a2,        // [B]
                     float* __restrict__ out_itdl,      // [B, 2048]
                     float* __restrict__ out_otdl)      // [B, 64]
{
    __shared__ float4 s_iw[DI4];             // 8 KB

    const int tid  = threadIdx.x;
    const int gtid = blockIdx.x * blockDim.x + tid;
    const int b    = gtid >> 5;              // warp id == batch row
    const int lane = gtid & 31;

    // Cooperative fill of the weight tile (256 threads x 2 float4).
    const float4* __restrict__ iw4 = reinterpret_cast<const float4*>(iw);
    #pragma unroll
    for (int k = 0; k < DI4 / 256; ++k)
        s_iw[k * 256 + tid] = iw4[k * 256 + tid];
    __syncthreads();

    if (b >= BATCH) return;

    const float4* __restrict__ it4  = reinterpret_cast<const float4*>(itdl) + (size_t)b * DI4;
    float4*       __restrict__ nit4 = reinterpret_cast<float4*>(out_itdl)   + (size_t)b * DI4;

    // Small streams early: latency overlaps the main loop.
    const float2 iv = __ldcs(reinterpret_cast<const float2*>(input) + (size_t)b * (NIN / 2) + lane);
    const float2 ov = __ldcs(reinterpret_cast<const float2*>(otdl)  + (size_t)b * (DO  / 2) + lane);

    float acc = 0.0f;

    // Depth-PF rolling prefetch over 16 float4 per lane.
    float4 x[PF];
    #pragma unroll
    for (int j = 0; j < PF; ++j)
        x[j] = __ldcs(it4 + j * 32 + lane);

    #pragma unroll
    for (int j = 0; j < 16; ++j) {
        const float4 cur = x[j % PF];
        if (j + PF < 16)
            x[j % PF] = __ldcs(it4 + (j + PF) * 32 + lane);

        const int v = j * 32 + lane;
        const float4 w = s_iw[v];            // LDS: broadcast-free of L1tex queue
        acc = fmaf(cur.x, w.x, acc);
        acc = fmaf(cur.y, w.y, acc);
        acc = fmaf(cur.z, w.z, acc);
        acc = fmaf(cur.w, w.w, acc);
        if (v >= SHIFT4) __stcs(nit4 + (v - SHIFT4), cur);
    }

    // Append input[b, 0:64] at itdl_new[b, 1984:2048] (float2-aligned).
    __stcs(reinterpret_cast<float2*>(out_itdl + (size_t)b * DI + (DI - NIN)) + lane, iv);

    // otdl: dot with ow + shift-by-1 store.
    float* __restrict__ no = out_otdl + (size_t)b * DO;
    {
        const float2 w2 = reinterpret_cast<const float2*>(ow)[lane];
        acc = fmaf(ov.x, w2.x, acc);
        acc = fmaf(ov.y, w2.y, acc);
        // otdl_new[t] = otdl[t+1]: elem 2*lane -> slot 2*lane-1, elem 2*lane+1 -> slot 2*lane.
        if (lane > 0) __stcs(no + 2 * lane - 1, ov.x);
        __stcs(no + 2 * lane, ov.y);
    }

    // Warp butterfly reduction.
    #pragma unroll
    for (int off = 16; off > 0; off >>= 1)
        acc += __shfl_xor_sync(0xffffffffu, acc, off);

    if (lane == 0) {
        const float a2 = acc + bias[0];
        out_a2[b] = a2;
        __stcs(no + (DO - 1), a2);
    }
}

extern "C" void kernel_launch(void* const* d_in, const int* in_sizes, int n_in,
                              void* d_out, int out_size) {
    const float* input = (const float*)d_in[0];
    const float* itdl  = (const float*)d_in[1];
    const float* otdl  = (const float*)d_in[2];
    const float* iw    = (const float*)d_in[3];
    const float* ow    = (const float*)d_in[4];
    const float* bias  = (const float*)d_in[5];

    float* out      = (float*)d_out;
    float* out_a2   = out;
    float* out_itdl = out + BATCH;
    float* out_otdl = out + BATCH + (size_t)BATCH * DI;

    const int threads = 256;                    // 8 warps -> 8 rows/CTA
    const int blocks  = BATCH / (threads / 32); // 2048

    arx_cell_kernel<<<blocks, threads>>>(input, itdl, otdl, iw, ow, bias,
                                         out_a2, out_itdl, out_otdl);
}

// round 10
// speedup vs baseline: 1.0068x; 1.0068x over previous
#include <cuda_runtime.h>

// ARXCell, B = 16384 rows:
//   a2[b]       = dot(iw, itdl[b,0:2048]) + dot(ow, otdl[b,0:64]) + bias
//   itdl_new[b] = [ itdl[b,64:2048], input[b,0:64] ]
//   otdl_new[b] = [ otdl[b,1:64], a2[b] ]
//   outputs[b]  = a2[b]
//
// Output layout: [ outputs(16384) | itdl_new(16384*2048) | otdl_new(16384*64) ]
//
// One warp per row, 2048 CTAs x 256 threads, occ-4 (64-reg budget). Depth-6
// rolling prefetch on the itdl stream, iw read directly (L1-resident
// broadcast). Reduction done BEFORE the otdl store so the shift-by-1 write is
// a single coalesced float2 per lane via shfl_down.

#define BATCH       16384
#define DI          2048
#define DO          64
#define NIN         64
#define DI4         (DI / 4)     // 512 float4 per row
#define SHIFT4      (NIN / 4)    // 16 float4 shift
#define PF          6            // prefetch depth

__global__ __launch_bounds__(256, 4)
void arx_cell_kernel(const float* __restrict__ input,   // [B, 64]
                     const float* __restrict__ itdl,    // [B, 2048]
                     const float* __restrict__ otdl,    // [B, 64]
                     const float* __restrict__ iw,      // [2048]
                     const float* __restrict__ ow,      // [64]
                     const float* __restrict__ bias,    // [1]
                     float* __restrict__ out_a2,        // [B]
                     float* __restrict__ out_itdl,      // [B, 2048]
                     float* __restrict__ out_otdl)      // [B, 64]
{
    const int gtid = blockIdx.x * blockDim.x + threadIdx.x;
    const int b    = gtid >> 5;          // warp id == batch row
    const int lane = gtid & 31;
    if (b >= BATCH) return;

    const float4* __restrict__ it4  = reinterpret_cast<const float4*>(itdl) + (size_t)b * DI4;
    float4*       __restrict__ nit4 = reinterpret_cast<float4*>(out_itdl)   + (size_t)b * DI4;
    const float4* __restrict__ iw4  = reinterpret_cast<const float4*>(iw);

    // Small streams early: latency overlaps the main loop.
    const float2 iv = __ldcs(reinterpret_cast<const float2*>(input) + (size_t)b * (NIN / 2) + lane);
    const float2 ov = __ldcs(reinterpret_cast<const float2*>(otdl)  + (size_t)b * (DO  / 2) + lane);

    float acc = 0.0f;

    // Depth-PF rolling prefetch over 16 float4 per lane.
    float4 x[PF];
    #pragma unroll
    for (int j = 0; j < PF; ++j)
        x[j] = __ldcs(it4 + j * 32 + lane);

    #pragma unroll
    for (int j = 0; j < 16; ++j) {
        const float4 cur = x[j % PF];
        if (j + PF < 16)
            x[j % PF] = __ldcs(it4 + (j + PF) * 32 + lane);

        const int v = j * 32 + lane;
        const float4 w = iw4[v];             // 8 KB, L1-resident broadcast
        acc = fmaf(cur.x, w.x, acc);
        acc = fmaf(cur.y, w.y, acc);
        acc = fmaf(cur.z, w.z, acc);
        acc = fmaf(cur.w, w.w, acc);
        if (v >= SHIFT4) __stcs(nit4 + (v - SHIFT4), cur);
    }

    // Append input[b, 0:64] at itdl_new[b, 1984:2048] (float2-aligned).
    __stcs(reinterpret_cast<float2*>(out_itdl + (size_t)b * DI + (DI - NIN)) + lane, iv);

    // otdl dot contribution.
    {
        const float2 w2 = reinterpret_cast<const float2*>(ow)[lane];
        acc = fmaf(ov.x, w2.x, acc);
        acc = fmaf(ov.y, w2.y, acc);
    }

    // Warp butterfly reduction (all lanes end with the full sum).
    #pragma unroll
    for (int off = 16; off > 0; off >>= 1)
        acc += __shfl_xor_sync(0xffffffffu, acc, off);
    const float a2 = acc + bias[0];

    // otdl shift-by-1, fully coalesced: lane stores float2 at slots
    // {2*lane, 2*lane+1} = { otdl[2*lane+1], otdl[2*lane+2] }; slot 63 = a2.
    {
        const float nxt = __shfl_down_sync(0xffffffffu, ov.x, 1);
        float2 o2;
        o2.x = ov.y;
        o2.y = (lane == 31) ? a2 : nxt;
        __stcs(reinterpret_cast<float2*>(out_otdl + (size_t)b * DO) + lane, o2);
    }

    if (lane == 0)
        out_a2[b] = a2;
}

extern "C" void kernel_launch(void* const* d_in, const int* in_sizes, int n_in,
                              void* d_out, int out_size) {
    const float* input = (const float*)d_in[0];
    const float* itdl  = (const float*)d_in[1];
    const float* otdl  = (const float*)d_in[2];
    const float* iw    = (const float*)d_in[3];
    const float* ow    = (const float*)d_in[4];
    const float* bias  = (const float*)d_in[5];

    float* out      = (float*)d_out;
    float* out_a2   = out;
    float* out_itdl = out + BATCH;
    float* out_otdl = out + BATCH + (size_t)BATCH * DI;

    const int threads = 256;                    // 8 warps -> 8 rows/CTA
    const int blocks  = BATCH / (threads / 32); // 2048

    arx_cell_kernel<<<blocks, threads>>>(input, itdl, otdl, iw, ow, bias,
                                         out_a2, out_itdl, out_otdl);
}

// round 11
// speedup vs baseline: 1.0428x; 1.0358x over previous
#include <cuda_runtime.h>

// ARXCell, B = 16384 rows:
//   a2[b]       = dot(iw, itdl[b,0:2048]) + dot(ow, otdl[b,0:64]) + bias
//   itdl_new[b] = [ itdl[b,64:2048], input[b,0:64] ]
//   otdl_new[b] = [ otdl[b,1:64], a2[b] ]
//   outputs[b]  = a2[b]
//
// Output layout: [ outputs(16384) | itdl_new(16384*2048) | otdl_new(16384*64) ]
//
// Final consolidated design (best measured across R1-R9):
//  - one warp per row, 2048 CTAs x 256 threads, occ-4 (64-reg budget)
//  - depth-4 rolling prefetch on the itdl stream (best measured: 38.98us);
//    8 warps x ~4 LDG.128 x 4 lines stays under the ~248-entry L1tex queue
//    while keeping enough stream bytes in flight per SM
//  - itdl read ONCE: feeds the dot product AND the shifted STG.128
//  - iw (8 KB) read directly, L1-resident broadcast (smem staging regressed)
//  - otdl shift-by-1 emitted as one coalesced float2 per lane via shfl
// Measured ~7.2 TB/s effective (~90% of spec) on the mandatory 280 MB stream.

#define BATCH       16384
#define DI          2048
#define DO          64
#define NIN         64
#define DI4         (DI / 4)     // 512 float4 per row
#define SHIFT4      (NIN / 4)    // 16 float4 shift
#define PF          4            // prefetch depth (best measured)

__global__ __launch_bounds__(256, 4)
void arx_cell_kernel(const float* __restrict__ input,   // [B, 64]
                     const float* __restrict__ itdl,    // [B, 2048]
                     const float* __restrict__ otdl,    // [B, 64]
                     const float* __restrict__ iw,      // [2048]
                     const float* __restrict__ ow,      // [64]
                     const float* __restrict__ bias,    // [1]
                     float* __restrict__ out_a2,        // [B]
                     float* __restrict__ out_itdl,      // [B, 2048]
                     float* __restrict__ out_otdl)      // [B, 64]
{
    const int gtid = blockIdx.x * blockDim.x + threadIdx.x;
    const int b    = gtid >> 5;          // warp id == batch row
    const int lane = gtid & 31;
    if (b >= BATCH) return;

    const float4* __restrict__ it4  = reinterpret_cast<const float4*>(itdl) + (size_t)b * DI4;
    float4*       __restrict__ nit4 = reinterpret_cast<float4*>(out_itdl)   + (size_t)b * DI4;
    const float4* __restrict__ iw4  = reinterpret_cast<const float4*>(iw);

    // Small streams early: latency overlaps the main loop.
    const float2 iv = __ldcs(reinterpret_cast<const float2*>(input) + (size_t)b * (NIN / 2) + lane);
    const float2 ov = __ldcs(reinterpret_cast<const float2*>(otdl)  + (size_t)b * (DO  / 2) + lane);

    float acc = 0.0f;

    // Depth-4 rolling prefetch over 16 float4 per lane.
    float4 x[PF];
    #pragma unroll
    for (int j = 0; j < PF; ++j)
        x[j] = __ldcs(it4 + j * 32 + lane);

    #pragma unroll
    for (int j = 0; j < 16; ++j) {
        const float4 cur = x[j & (PF - 1)];
        if (j + PF < 16)
            x[j & (PF - 1)] = __ldcs(it4 + (j + PF) * 32 + lane);

        const int v = j * 32 + lane;
        const float4 w = iw4[v];             // 8 KB, L1-resident broadcast
        acc = fmaf(cur.x, w.x, acc);
        acc = fmaf(cur.y, w.y, acc);
        acc = fmaf(cur.z, w.z, acc);
        acc = fmaf(cur.w, w.w, acc);
        if (v >= SHIFT4) __stcs(nit4 + (v - SHIFT4), cur);
    }

    // Append input[b, 0:64] at itdl_new[b, 1984:2048] (float2-aligned).
    __stcs(reinterpret_cast<float2*>(out_itdl + (size_t)b * DI + (DI - NIN)) + lane, iv);

    // otdl dot contribution.
    {
        const float2 w2 = reinterpret_cast<const float2*>(ow)[lane];
        acc = fmaf(ov.x, w2.x, acc);
        acc = fmaf(ov.y, w2.y, acc);
    }

    // Warp butterfly reduction (all lanes end with the full sum).
    #pragma unroll
    for (int off = 16; off > 0; off >>= 1)
        acc += __shfl_xor_sync(0xffffffffu, acc, off);
    const float a2 = acc + bias[0];

    // otdl shift-by-1, fully coalesced: lane stores float2 at slots
    // {2*lane, 2*lane+1} = { otdl[2*lane+1], otdl[2*lane+2] }; slot 63 = a2.
    {
        const float nxt = __shfl_down_sync(0xffffffffu, ov.x, 1);
        float2 o2;
        o2.x = ov.y;
        o2.y = (lane == 31) ? a2 : nxt;
        __stcs(reinterpret_cast<float2*>(out_otdl + (size_t)b * DO) + lane, o2);
    }

    if (lane == 0)
        out_a2[b] = a2;
}

extern "C" void kernel_launch(void* const* d_in, const int* in_sizes, int n_in,
                              void* d_out, int out_size) {
    const float* input = (const float*)d_in[0];
    const float* itdl  = (const float*)d_in[1];
    const float* otdl  = (const float*)d_in[2];
    const float* iw    = (const float*)d_in[3];
    const float* ow    = (const float*)d_in[4];
    const float* bias  = (const float*)d_in[5];

    float* out      = (float*)d_out;
    float* out_a2   = out;
    float* out_itdl = out + BATCH;
    float* out_otdl = out + BATCH + (size_t)BATCH * DI;

    const int threads = 256;                    // 8 warps -> 8 rows/CTA
    const int blocks  = BATCH / (threads / 32); // 2048

    arx_cell_kernel<<<blocks, threads>>>(input, itdl, otdl, iw, ow, bias,
                                         out_a2, out_itdl, out_otdl);
}